// round 1
// baseline (speedup 1.0000x reference)
#include <cuda_runtime.h>

namespace {
constexpr int BS = 4;
constexpr int P  = 4096;
constexpr int HW = 512 * 512;
constexpr int TILE = 128;
constexpr int NT = P / TILE;              // 32 tiles per dim
constexpr int NTILES = NT * (NT + 1) / 2; // 528 upper-tri tiles (incl. diagonal)
constexpr double N_PAIRS = 8386560.0;     // P*(P-1)/2
}

// Scratch (allocation-free: __device__ globals)
__device__ float  g_pred[BS][P];
__device__ float  g_relu[BS][P];
__device__ int    g_truev[BS][P];
__device__ double g_acc;

__global__ void gather_k(const float* __restrict__ yp,
                         const int*   __restrict__ yt,
                         const int*   __restrict__ sm) {
    int tid = blockIdx.x * blockDim.x + threadIdx.x;
    if (tid == 0) g_acc = 0.0;
    if (tid < BS * P) {
        int b = tid >> 12;           // /4096
        int p = tid & (P - 1);
        int idx = sm[tid];
        float v = yp[b * HW + idx];
        g_pred[b][p]  = v;
        g_relu[b][p]  = fmaxf(v, 0.0f);
        g_truev[b][p] = yt[b * HW + idx];
    }
}

__device__ __forceinline__ float huber_f(float y) {
    // theta=0.1: y<0.1 -> 5*y*y ; else y-0.05  (C^1, tangent at 0.1)
    float q = 5.0f * y * y;
    float l = y - 0.05f;
    return (y < 0.1f) ? q : l;
}

__global__ __launch_bounds__(256, 4) void pair_k() {
    int b = blockIdx.x / NTILES;
    int t = blockIdx.x % NTILES;
    // decode upper-tri tile (ti <= tj); uniform per block, cost negligible
    int ti = 0;
    while (t >= NT - ti) { t -= NT - ti; ti++; }
    int tj = ti + t;
    int i0 = ti * TILE, j0 = tj * TILE;

    __shared__ float s_a[TILE];  __shared__ int s_ta[TILE];
    __shared__ float s_c[TILE];  __shared__ int s_tc[TILE];

    if (threadIdx.x < TILE) {
        int u = threadIdx.x;
        s_a[u]  = g_pred[b][i0 + u];
        s_ta[u] = g_truev[b][i0 + u];
    } else {
        int u = threadIdx.x - TILE;
        s_c[u]  = g_relu[b][j0 + u];
        s_tc[u] = g_truev[b][j0 + u];
    }
    __syncthreads();

    int tx = threadIdx.x & 15;   // col group
    int ty = threadIdx.x >> 4;   // row group

    float a[8]; int ta[8]; float c[8]; int tc[8];
    #pragma unroll
    for (int k = 0; k < 8; k++) {
        a[k]  = s_a[ty * 8 + k];
        ta[k] = s_ta[ty * 8 + k];
        c[k]  = s_c[tx * 8 + k];
        tc[k] = s_tc[tx * 8 + k];
    }

    float acc = 0.0f;
    if (ti != tj) {
        // fully interior tile: every (i, j) pair valid (j > i guaranteed)
        #pragma unroll
        for (int jj = 0; jj < 8; jj++) {
            float cj = c[jj]; int tcv = tc[jj];
            #pragma unroll
            for (int ii = 0; ii < 8; ii++) {
                float d = a[ii] - cj;
                float p = fmaxf(d, 0.0f);            // pi_pred
                bool eq = (ta[ii] == tcv);
                float y = eq ? p : (1.0f - p);       // huber arg
                float s = eq ? 3.0f : 1.0f;          // weight
                acc = fmaf(s, huber_f(y), acc);
            }
        }
    } else {
        // diagonal tile: mask j > i
        int ib = ty * 8, jb = tx * 8;
        #pragma unroll
        for (int jj = 0; jj < 8; jj++) {
            float cj = c[jj]; int tcv = tc[jj];
            #pragma unroll
            for (int ii = 0; ii < 8; ii++) {
                if (jb + jj > ib + ii) {
                    float d = a[ii] - cj;
                    float p = fmaxf(d, 0.0f);
                    bool eq = (ta[ii] == tcv);
                    float y = eq ? p : (1.0f - p);
                    float s = eq ? 3.0f : 1.0f;
                    acc = fmaf(s, huber_f(y), acc);
                }
            }
        }
    }

    // warp reduce
    #pragma unroll
    for (int o = 16; o; o >>= 1)
        acc += __shfl_xor_sync(0xffffffffu, acc, o);

    __shared__ float s_part[8];
    int warp = threadIdx.x >> 5, lane = threadIdx.x & 31;
    if (lane == 0) s_part[warp] = acc;
    __syncthreads();
    if (threadIdx.x == 0) {
        float s = 0.0f;
        #pragma unroll
        for (int k = 0; k < 8; k++) s += s_part[k];
        atomicAdd(&g_acc, (double)s);
    }
}

__global__ void final_k(float* out) {
    out[0] = (float)(g_acc / (N_PAIRS * (double)BS));
}

extern "C" void kernel_launch(void* const* d_in, const int* in_sizes, int n_in,
                              void* d_out, int out_size) {
    const float* yp = (const float*)d_in[0];
    const int*   yt = (const int*)d_in[1];
    const int*   sm = (const int*)d_in[2];

    gather_k<<<(BS * P + 255) / 256, 256>>>(yp, yt, sm);
    pair_k<<<BS * NTILES, 256>>>();
    final_k<<<1, 1>>>((float*)d_out);
}

// round 2
// speedup vs baseline: 1.0013x; 1.0013x over previous
#include <cuda_runtime.h>

namespace {
constexpr int BS = 4;
constexpr int P  = 4096;
constexpr int HW = 512 * 512;
constexpr int TILE = 128;
constexpr int NT = P / TILE;              // 32 tiles per dim
constexpr int NTILES = NT * (NT + 1) / 2; // 528 upper-tri tiles (incl. diagonal)
constexpr double N_PAIRS = 8386560.0;     // P*(P-1)/2
}

__device__ double g_acc;   // static-init 0; final_k resets it each replay

__global__ __launch_bounds__(256) void pair_k(const float* __restrict__ yp,
                                              const int*   __restrict__ yt,
                                              const int*   __restrict__ sm) {
    int b = blockIdx.x / NTILES;
    int t = blockIdx.x % NTILES;
    // decode upper-tri tile (ti <= tj); uniform per block
    int ti = 0;
    while (t >= NT - ti) { t -= NT - ti; ti++; }
    int tj = ti + t;
    int i0 = ti * TILE, j0 = tj * TILE;

    __shared__ float s_a[TILE];  __shared__ int s_ta[TILE];   // row: pred, label
    __shared__ float s_nc[TILE]; __shared__ int s_tc[TILE];   // col: -relu(pred), label

    // fused gather: coalesced idx load, then scattered data loads (L2-resident
    // after first wave; each element reused ~33x across tiles)
    if (threadIdx.x < TILE) {
        int u = threadIdx.x;
        int idx = sm[b * P + i0 + u];
        s_a[u]  = yp[b * HW + idx];
        s_ta[u] = yt[b * HW + idx];
    } else {
        int u = threadIdx.x - TILE;
        int idx = sm[b * P + j0 + u];
        float v = yp[b * HW + idx];
        s_nc[u] = -fmaxf(v, 0.0f);
        s_tc[u] = yt[b * HW + idx];
    }
    __syncthreads();

    int tx = threadIdx.x & 15;   // col group
    int ty = threadIdx.x >> 4;   // row group

    float a[8]; int ta[8]; float nc[8]; int tc[8];
    #pragma unroll
    for (int k = 0; k < 8; k++) {
        a[k]  = s_a[ty * 8 + k];
        ta[k] = s_ta[ty * 8 + k];
        nc[k] = s_nc[tx * 8 + k];
        tc[k] = s_tc[tx * 8 + k];
    }

    float acc0 = 0.0f, acc1 = 0.0f;
    if (ti != tj) {
        // interior tile: all 64 pairs valid (j > i guaranteed)
        #pragma unroll
        for (int jj = 0; jj < 8; jj++) {
            float cj = nc[jj]; int tcv = tc[jj];
            #pragma unroll
            for (int ii = 0; ii < 8; ii++) {
                float d = a[ii] + cj;                 // pred_i - relu_j
                float p = fmaxf(d, 0.0f);             // pi_pred
                float q = 1.0f - p;
                bool eq = (ta[ii] == tcv);
                float y = eq ? p : q;
                // huber(y) = 5*z^2 + (y - z), z = min(y, 0.1)  (exact identity)
                float z = fminf(y, 0.1f);
                float w = y - z;
                float h = fmaf(z * z, 5.0f, w);
                float s = eq ? 3.0f : 1.0f;
                if (ii & 1) acc1 = fmaf(s, h, acc1);
                else        acc0 = fmaf(s, h, acc0);
            }
        }
    } else {
        // diagonal tile: mask j > i
        int ib = ty * 8, jb = tx * 8;
        #pragma unroll
        for (int jj = 0; jj < 8; jj++) {
            float cj = nc[jj]; int tcv = tc[jj];
            #pragma unroll
            for (int ii = 0; ii < 8; ii++) {
                if (jb + jj > ib + ii) {
                    float d = a[ii] + cj;
                    float p = fmaxf(d, 0.0f);
                    float q = 1.0f - p;
                    bool eq = (ta[ii] == tcv);
                    float y = eq ? p : q;
                    float z = fminf(y, 0.1f);
                    float w = y - z;
                    float h = fmaf(z * z, 5.0f, w);
                    float s = eq ? 3.0f : 1.0f;
                    if (ii & 1) acc1 = fmaf(s, h, acc1);
                    else        acc0 = fmaf(s, h, acc0);
                }
            }
        }
    }
    float acc = acc0 + acc1;

    // warp reduce
    #pragma unroll
    for (int o = 16; o; o >>= 1)
        acc += __shfl_xor_sync(0xffffffffu, acc, o);

    __shared__ float s_part[8];
    int warp = threadIdx.x >> 5, lane = threadIdx.x & 31;
    if (lane == 0) s_part[warp] = acc;
    __syncthreads();
    if (threadIdx.x == 0) {
        float ssum = 0.0f;
        #pragma unroll
        for (int k = 0; k < 8; k++) ssum += s_part[k];
        atomicAdd(&g_acc, (double)ssum);
    }
}

__global__ void final_k(float* out) {
    out[0] = (float)(g_acc / (N_PAIRS * (double)BS));
    g_acc = 0.0;   // restore invariant for next graph replay (deterministic)
}

extern "C" void kernel_launch(void* const* d_in, const int* in_sizes, int n_in,
                              void* d_out, int out_size) {
    const float* yp = (const float*)d_in[0];
    const int*   yt = (const int*)d_in[1];
    const int*   sm = (const int*)d_in[2];

    pair_k<<<BS * NTILES, 256>>>(yp, yt, sm);
    final_k<<<1, 1>>>((float*)d_out);
}